// round 3
// baseline (speedup 1.0000x reference)
#include <cuda_runtime.h>

// Fixed problem shape
#define CC      20
#define HW_     (512 * 512)           // 262144 = 2^18
#define BATCH_  8
#define NPIX    (BATCH_ * HW_)        // 2,097,152 pixels
#define THREADS 256
#define PPT     4                     // pixels per thread (float4 / int4 loads)
#define GRID    (NPIX / (THREADS * PPT))   // 2048 blocks

// Per-block deterministic partials (overwritten every launch; no init needed)
__device__ float        g_part0[GRID];
__device__ float        g_part1[GRID];
__device__ float        g_part2[GRID];
__device__ unsigned int g_count = 0;   // last-block-done counter (self-resetting)

__device__ __forceinline__ void block_reduce3(float& a0, float& a1, float& a2,
                                              float* sm0, float* sm1, float* sm2)
{
#pragma unroll
    for (int off = 16; off > 0; off >>= 1) {
        a0 += __shfl_down_sync(0xFFFFFFFFu, a0, off);
        a1 += __shfl_down_sync(0xFFFFFFFFu, a1, off);
        a2 += __shfl_down_sync(0xFFFFFFFFu, a2, off);
    }
    const int lane = threadIdx.x & 31;
    const int wid  = threadIdx.x >> 5;
    if (lane == 0) { sm0[wid] = a0; sm1[wid] = a1; sm2[wid] = a2; }
    __syncthreads();
    if (wid == 0) {
        const int nw = THREADS / 32;
        a0 = (lane < nw) ? sm0[lane] : 0.f;
        a1 = (lane < nw) ? sm1[lane] : 0.f;
        a2 = (lane < nw) ? sm2[lane] : 0.f;
#pragma unroll
        for (int off = 4; off > 0; off >>= 1) {
            a0 += __shfl_down_sync(0xFFFFFFFFu, a0, off);
            a1 += __shfl_down_sync(0xFFFFFFFFu, a1, off);
            a2 += __shfl_down_sync(0xFFFFFFFFu, a2, off);
        }
    }
}

__global__ __launch_bounds__(THREADS)
void tce_kernel(const float* __restrict__ logits,
                const int*   __restrict__ targets,
                float* __restrict__ out, int out_size)
{
    const int q = (blockIdx.x * THREADS + threadIdx.x) * PPT;  // first pixel
    const int b = q >> 18;            // q / HW_
    const int s = q & (HW_ - 1);      // q % HW_
    const float* base = logits + (size_t)b * CC * HW_ + s;

    const int4 tg4 = *reinterpret_cast<const int4*>(targets + q);
    const int tgt[4] = {tg4.x, tg4.y, tg4.z, tg4.w};

    // grp[g][j]: sum of exp over 5-channel group g for pixel j.
    // No max-subtraction: softmax is shift-invariant and |logit| is small,
    // so exp(x) is exactly representable-range-safe in fp32.
    float grp[4][4];
    float pt[4];
#pragma unroll
    for (int g = 0; g < 4; ++g)
#pragma unroll
        for (int j = 0; j < 4; ++j) grp[g][j] = 0.f;
#pragma unroll
    for (int j = 0; j < 4; ++j) pt[j] = 0.f;

#pragma unroll
    for (int c = 0; c < CC; ++c) {
        const float4 v = *reinterpret_cast<const float4*>(base + (size_t)c * HW_);
        const int g = c / 5;                 // compile-time per iteration
        const float e0 = __expf(v.x);
        const float e1 = __expf(v.y);
        const float e2 = __expf(v.z);
        const float e3 = __expf(v.w);
        grp[g][0] += e0;  pt[0] = (c == tgt[0]) ? e0 : pt[0];
        grp[g][1] += e1;  pt[1] = (c == tgt[1]) ? e1 : pt[1];
        grp[g][2] += e2;  pt[2] = (c == tgt[2]) ? e2 : pt[2];
        grp[g][3] += e3;  pt[3] = (c == tgt[3]) ? e3 : pt[3];
    }

    float a0 = 0.f, a1 = 0.f, a2 = 0.f;      // sums of log p per level
#pragma unroll
    for (int j = 0; j < 4; ++j) {
        const int t = tgt[j];
        const float lo = grp[0][j] + grp[1][j];
        const float hi = grp[2][j] + grp[3][j];
        const float total = lo + hi;
        const float g10 = (t < 10) ? lo : hi;
        const float g5  = (t < 5) ? grp[0][j]
                        : (t < 10) ? grp[1][j]
                        : (t < 15) ? grp[2][j]
                        : grp[3][j];
        const float inv = __fdividef(1.0f, total);
        const float p0 = fminf(fmaxf(g10   * inv, 1e-7f), 0.9999999f);
        const float p1 = fminf(fmaxf(g5    * inv, 1e-7f), 0.9999999f);
        const float p2 = fminf(fmaxf(pt[j] * inv, 1e-7f), 0.9999999f);
        a0 += __logf(p0);
        a1 += __logf(p1);
        a2 += __logf(p2);
    }

    __shared__ float sm0[THREADS / 32], sm1[THREADS / 32], sm2[THREADS / 32];
    block_reduce3(a0, a1, a2, sm0, sm1, sm2);

    // Thread 0 publishes this block's partials (deterministic per block).
    __shared__ bool is_last;
    if (threadIdx.x == 0) {
        g_part0[blockIdx.x] = a0;
        g_part1[blockIdx.x] = a1;
        g_part2[blockIdx.x] = a2;
        __threadfence();
        const unsigned prev = atomicAdd(&g_count, 1u);
        is_last = (prev == GRID - 1);
    }
    __syncthreads();

    if (!is_last) return;

    // ---- last block: reduce all 2048 partials in fixed order, write output ----
    float r0 = 0.f, r1 = 0.f, r2 = 0.f;
#pragma unroll
    for (int i = threadIdx.x; i < GRID; i += THREADS) {
        r0 += g_part0[i];
        r1 += g_part1[i];
        r2 += g_part2[i];
    }
    block_reduce3(r0, r1, r2, sm0, sm1, sm2);

    if (threadIdx.x == 0) {
        const double n  = (double)NPIX;
        const double l0 = -(double)r0 / n;
        const double l1 = -(double)r1 / n;
        const double l2 = -(double)r2 / n;
        const double tot = l0 + l1 + l2;

        if (out_size == 3) {                 // levels-only fallback layout
            out[0] = (float)l0; out[1] = (float)l1; out[2] = (float)l2;
        } else {                             // (loss, level_losses) flattened
            if (out_size > 0) out[0] = (float)tot;
            if (out_size > 1) out[1] = (float)l0;
            if (out_size > 2) out[2] = (float)l1;
            if (out_size > 3) out[3] = (float)l2;
            for (int i = 4; i < out_size; ++i) out[i] = 0.f;
        }
        g_count = 0;                         // self-restore for next graph replay
    }
}

extern "C" void kernel_launch(void* const* d_in, const int* in_sizes, int n_in,
                              void* d_out, int out_size) {
    const float* logits  = (const float*)d_in[0];
    const int*   targets = (const int*)d_in[1];
    float*       out     = (float*)d_out;

    tce_kernel<<<GRID, THREADS>>>(logits, targets, out, out_size);
}